// round 12
// baseline (speedup 1.0000x reference)
#include <cuda_runtime.h>
#include <cuda_fp16.h>
#include <cstdint>

// Problem constants
#define BATCH   16384
#define MAXF    32
#define NFEAT   768
#define FT_OUT  1024
#define FULL_MASK 0xFFFFFFFFu

// Slice config: 8 column-slices of 128 cols (256 B of fp16 per row-slice).
// Per-SM gather footprint = 768 rows * 256 B = 192 KB -> fits in L1 (228 KB).
#define NSLICE       8
#define SLICE_COLS   128
#define SBLOCKS      (BATCH / 8)          // 2048 sample-blocks (8 samples per CTA)
#define ROW_BYTES    (FT_OUT * 2)         // 2048

// Device globals
__device__ __half g_ftw_h[NFEAT * FT_OUT];     // fp16 table (1.5 MB, L2-resident)
__device__ float  g_part[BATCH * NSLICE];      // per-(sample,slice) partials

// ---------------------------------------------------------------------------
// Kernel 1: ft_w fp32 -> fp16 (one float4 per thread)
// ---------------------------------------------------------------------------
__global__ void convert_ftw_kernel(const float* __restrict__ ftw) {
    int i = blockIdx.x * blockDim.x + threadIdx.x;
    float4 v = reinterpret_cast<const float4*>(ftw)[i];
    __half2* dst = reinterpret_cast<__half2*>(g_ftw_h);
    dst[2 * i + 0] = __floats2half2_rn(v.x, v.y);
    dst[2 * i + 1] = __floats2half2_rn(v.z, v.w);
}

// ---------------------------------------------------------------------------
// Kernel 2: main — one warp per (sample, slice). Slice id in the HIGH bits of
// blockIdx so co-resident CTAs share a slice -> table slice is L1-resident.
// Per feature per warp: 2x LDG.64 (fully-sectored 256 B) + 4 HFMA2;
// meta via uniform LDS.128 (2 features per read).
// ---------------------------------------------------------------------------
__global__ void __launch_bounds__(256, 5)
nnue_slice_kernel(const float* __restrict__ values,
                  const int*   __restrict__ stm_idx,
                  const int*   __restrict__ nstm_idx,
                  const float* __restrict__ ft_b,
                  const float* __restrict__ out_w)
{
    __shared__ uint2 s_meta[8][MAXF];   // [sampleInCta][feature] = {idxS|idxN<<16, valbits}

    const int tid  = threadIdx.x;
    const int w    = tid >> 5;
    const int lane = tid & 31;
    const int q    = blockIdx.x >> 11;        // slice 0..7 (contiguous 2048-CTA groups)
    const int sb   = blockIdx.x & (SBLOCKS - 1);
    const int b    = sb * 8 + w;              // this warp's sample

    // Stage metadata: 256 threads, one (sample, feature) each
    {
        const int s = tid >> 5;
        const int f = tid & 31;
        const int bg = sb * 8 + s;
        const int is = stm_idx [bg * MAXF + f];
        const int in = nstm_idx[bg * MAXF + f];
        const float v = values [bg * MAXF + f];
        s_meta[s][f] = make_uint2((unsigned)is | ((unsigned)in << 16),
                                  __float_as_uint(v));
    }
    __syncthreads();

    // Lane's 8-byte chunk within the slice: bytes [q*256 + lane*8, +8) of each row
    const char* W = reinterpret_cast<const char*>(g_ftw_h) + q * 256 + lane * 8;
    const uint4* meta4 = reinterpret_cast<const uint4*>(s_meta[w]);   // 2 feats/read

    __half2 aS0 = __half2half2(__float2half_rn(0.0f));
    __half2 aS1 = aS0, aN0 = aS0, aN1 = aS0;

    #pragma unroll 4
    for (int c = 0; c < 16; ++c) {            // 2 features per iteration
        const uint4 m = meta4[c];             // uniform LDS.128 broadcast
        const __half2 v0 = __float2half2_rn(__uint_as_float(m.y));
        const __half2 v1 = __float2half2_rn(__uint_as_float(m.w));

        // 4 independent LDG.64
        uint2 dS0 = *reinterpret_cast<const uint2*>(W + (size_t)(m.x & 0xFFFFu) * ROW_BYTES);
        uint2 dN0 = *reinterpret_cast<const uint2*>(W + (size_t)(m.x >> 16)     * ROW_BYTES);
        uint2 dS1 = *reinterpret_cast<const uint2*>(W + (size_t)(m.z & 0xFFFFu) * ROW_BYTES);
        uint2 dN1 = *reinterpret_cast<const uint2*>(W + (size_t)(m.z >> 16)     * ROW_BYTES);

        aS0 = __hfma2(v0, *reinterpret_cast<__half2*>(&dS0.x), aS0);
        aS1 = __hfma2(v0, *reinterpret_cast<__half2*>(&dS0.y), aS1);
        aN0 = __hfma2(v0, *reinterpret_cast<__half2*>(&dN0.x), aN0);
        aN1 = __hfma2(v0, *reinterpret_cast<__half2*>(&dN0.y), aN1);
        aS0 = __hfma2(v1, *reinterpret_cast<__half2*>(&dS1.x), aS0);
        aS1 = __hfma2(v1, *reinterpret_cast<__half2*>(&dS1.y), aS1);
        aN0 = __hfma2(v1, *reinterpret_cast<__half2*>(&dN1.x), aN0);
        aN1 = __hfma2(v1, *reinterpret_cast<__half2*>(&dN1.y), aN1);
    }

    // ----- epilogue: fp32 bias add, clip [0,1], dot with out_w -----
    // Lane owns cols q*128 + lane*4 .. +3 (both sides) -> float4 index q*32+lane
    const float4* fb4 = reinterpret_cast<const float4*>(ft_b);
    const float4* ow4 = reinterpret_cast<const float4*>(out_w);
    const int fidx = q * 32 + lane;

    float4 bb = fb4[fidx];
    float4 wS = ow4[fidx];
    float4 wN = ow4[256 + fidx];     // +256 float4 = +1024 cols (nstm half)

    float2 p0 = __half22float2(aS0), p1 = __half22float2(aS1);
    float2 r0 = __half22float2(aN0), r1 = __half22float2(aN1);

    float partial = 0.0f, hh;
    hh = fminf(fmaxf(p0.x + bb.x, 0.f), 1.f); partial = fmaf(hh, wS.x, partial);
    hh = fminf(fmaxf(p0.y + bb.y, 0.f), 1.f); partial = fmaf(hh, wS.y, partial);
    hh = fminf(fmaxf(p1.x + bb.z, 0.f), 1.f); partial = fmaf(hh, wS.z, partial);
    hh = fminf(fmaxf(p1.y + bb.w, 0.f), 1.f); partial = fmaf(hh, wS.w, partial);
    hh = fminf(fmaxf(r0.x + bb.x, 0.f), 1.f); partial = fmaf(hh, wN.x, partial);
    hh = fminf(fmaxf(r0.y + bb.y, 0.f), 1.f); partial = fmaf(hh, wN.y, partial);
    hh = fminf(fmaxf(r1.x + bb.z, 0.f), 1.f); partial = fmaf(hh, wN.z, partial);
    hh = fminf(fmaxf(r1.y + bb.w, 0.f), 1.f); partial = fmaf(hh, wN.w, partial);

    // warp reduce
    #pragma unroll
    for (int off = 16; off > 0; off >>= 1)
        partial += __shfl_xor_sync(FULL_MASK, partial, off);

    if (lane == 0) g_part[b * NSLICE + q] = partial;   // deterministic slot
}

// ---------------------------------------------------------------------------
// Kernel 3: sum 8 slice-partials + sigmoid
// ---------------------------------------------------------------------------
__global__ void final_kernel(const float* __restrict__ out_b,
                             float* __restrict__ out) {
    int b = blockIdx.x * 256 + threadIdx.x;
    const float4* p = reinterpret_cast<const float4*>(g_part + b * NSLICE);
    float4 a = p[0], c = p[1];
    float x = ((a.x + a.y) + (a.z + a.w)) + ((c.x + c.y) + (c.z + c.w)) + out_b[0];
    out[b] = 1.0f / (1.0f + __expf(-x));
}

// ---------------------------------------------------------------------------
// kernel_launch
// Inputs: values, stm_indices, nstm_indices, ft_w, ft_b, out_w, out_b
// ---------------------------------------------------------------------------
extern "C" void kernel_launch(void* const* d_in, const int* in_sizes, int n_in,
                              void* d_out, int out_size)
{
    const float* values   = (const float*)d_in[0];
    const int*   stm_idx  = (const int*)  d_in[1];
    const int*   nstm_idx = (const int*)  d_in[2];
    const float* ft_w     = (const float*)d_in[3];
    const float* ft_b     = (const float*)d_in[4];
    const float* out_w    = (const float*)d_in[5];
    const float* out_b    = (const float*)d_in[6];
    float*       out      = (float*)d_out;

    static bool attr_set = false;
    if (!attr_set) {
        cudaFuncSetAttribute(nnue_slice_kernel,
                             cudaFuncAttributePreferredSharedMemoryCarveout,
                             cudaSharedmemCarveoutMaxL1);
        attr_set = true;
    }

    convert_ftw_kernel<<<(NFEAT * FT_OUT / 4) / 256, 256>>>(ft_w);
    nnue_slice_kernel<<<NSLICE * SBLOCKS, 256>>>(values, stm_idx, nstm_idx,
                                                 ft_b, out_w);
    final_kernel<<<BATCH / 256, 256>>>(out_b, out);
}

// round 13
// speedup vs baseline: 1.2632x; 1.2632x over previous
#include <cuda_runtime.h>
#include <cuda_fp16.h>
#include <cstdint>

// Problem constants
#define BATCH   16384
#define MAXF    32
#define NFEAT   768
#define FT_OUT  1024
#define FULL_MASK 0xFFFFFFFFu
#define ROW_BYTES (FT_OUT * 2)     // 2048 B per fp16 row

// fp16 copy of ft_w, rebuilt every kernel_launch (deterministic).
__device__ __half g_ftw_h[NFEAT * FT_OUT];

// ---------------------------------------------------------------------------
// Kernel 1: ft_w fp32 -> fp16 (one float4 per thread)
// ---------------------------------------------------------------------------
__global__ void convert_ftw_kernel(const float* __restrict__ ftw) {
    int i = blockIdx.x * blockDim.x + threadIdx.x;
    float4 v = reinterpret_cast<const float4*>(ftw)[i];
    __half2* dst = reinterpret_cast<__half2*>(g_ftw_h);
    dst[2 * i + 0] = __floats2half2_rn(v.x, v.y);
    dst[2 * i + 1] = __floats2half2_rn(v.z, v.w);
}

// ---------------------------------------------------------------------------
// Kernel 2: ONE sample per CTA, 8 warps each owning 128 columns.
// Minimizes concurrent samples per SM (6 at 6 CTAs/SM) to cut L1 capacity
// thrash, while keeping 48 warps/SM for latency coverage.
// Per feature per warp: 2x LDG.64 (256 B contiguous, fully sectored)
// + 4 HFMA2; meta via uniform LDS.128 (2 features per read).
// ---------------------------------------------------------------------------
__global__ void __launch_bounds__(256, 6)
nnue_main_kernel(const float* __restrict__ values,
                 const int*   __restrict__ stm_idx,
                 const int*   __restrict__ nstm_idx,
                 const float* __restrict__ ft_b,
                 const float* __restrict__ out_w,
                 const float* __restrict__ out_b,
                 float*       __restrict__ out)
{
    __shared__ uint2 s_meta[MAXF];   // {idxS | idxN<<16, val bits}
    __shared__ float s_partial[8];

    const int tid  = threadIdx.x;
    const int w    = tid >> 5;
    const int lane = tid & 31;
    const int b    = blockIdx.x;     // one sample per CTA

    // Stage metadata: warp 0, one feature per lane
    if (tid < 32) {
        const int is = stm_idx [b * MAXF + tid];
        const int in = nstm_idx[b * MAXF + tid];
        const float v = values [b * MAXF + tid];
        s_meta[tid] = make_uint2((unsigned)is | ((unsigned)in << 16),
                                 __float_as_uint(v));
    }
    __syncthreads();

    // Warp w owns cols [w*128, w*128+128): byte offset w*256; lane's 8 B chunk.
    const char* W = reinterpret_cast<const char*>(g_ftw_h) + w * 256 + lane * 8;
    const uint4* meta4 = reinterpret_cast<const uint4*>(s_meta);   // 2 feats/read

    __half2 aS0 = __half2half2(__float2half_rn(0.0f));
    __half2 aS1 = aS0, aN0 = aS0, aN1 = aS0;

    #pragma unroll 4
    for (int c = 0; c < 16; ++c) {            // 2 features per iteration
        const uint4 m = meta4[c];             // uniform LDS.128 broadcast
        const __half2 v0 = __float2half2_rn(__uint_as_float(m.y));
        const __half2 v1 = __float2half2_rn(__uint_as_float(m.w));

        // 4 independent LDG.64
        uint2 dS0 = *reinterpret_cast<const uint2*>(W + (size_t)(m.x & 0xFFFFu) * ROW_BYTES);
        uint2 dN0 = *reinterpret_cast<const uint2*>(W + (size_t)(m.x >> 16)     * ROW_BYTES);
        uint2 dS1 = *reinterpret_cast<const uint2*>(W + (size_t)(m.z & 0xFFFFu) * ROW_BYTES);
        uint2 dN1 = *reinterpret_cast<const uint2*>(W + (size_t)(m.z >> 16)     * ROW_BYTES);

        aS0 = __hfma2(v0, *reinterpret_cast<__half2*>(&dS0.x), aS0);
        aS1 = __hfma2(v0, *reinterpret_cast<__half2*>(&dS0.y), aS1);
        aN0 = __hfma2(v0, *reinterpret_cast<__half2*>(&dN0.x), aN0);
        aN1 = __hfma2(v0, *reinterpret_cast<__half2*>(&dN0.y), aN1);
        aS0 = __hfma2(v1, *reinterpret_cast<__half2*>(&dS1.x), aS0);
        aS1 = __hfma2(v1, *reinterpret_cast<__half2*>(&dS1.y), aS1);
        aN0 = __hfma2(v1, *reinterpret_cast<__half2*>(&dN1.x), aN0);
        aN1 = __hfma2(v1, *reinterpret_cast<__half2*>(&dN1.y), aN1);
    }

    // ----- epilogue: fp32 bias add, clip [0,1], dot with out_w -----
    // Lane owns cols w*128 + lane*4 .. +3 (both sides) -> float4 index w*32+lane
    const float4* fb4 = reinterpret_cast<const float4*>(ft_b);
    const float4* ow4 = reinterpret_cast<const float4*>(out_w);
    const int fidx = w * 32 + lane;

    float4 bb = fb4[fidx];
    float4 wS = ow4[fidx];
    float4 wN = ow4[256 + fidx];     // +256 float4 = +1024 cols (nstm half)

    float2 p0 = __half22float2(aS0), p1 = __half22float2(aS1);
    float2 r0 = __half22float2(aN0), r1 = __half22float2(aN1);

    float partial = 0.0f, hh;
    hh = fminf(fmaxf(p0.x + bb.x, 0.f), 1.f); partial = fmaf(hh, wS.x, partial);
    hh = fminf(fmaxf(p0.y + bb.y, 0.f), 1.f); partial = fmaf(hh, wS.y, partial);
    hh = fminf(fmaxf(p1.x + bb.z, 0.f), 1.f); partial = fmaf(hh, wS.z, partial);
    hh = fminf(fmaxf(p1.y + bb.w, 0.f), 1.f); partial = fmaf(hh, wS.w, partial);
    hh = fminf(fmaxf(r0.x + bb.x, 0.f), 1.f); partial = fmaf(hh, wN.x, partial);
    hh = fminf(fmaxf(r0.y + bb.y, 0.f), 1.f); partial = fmaf(hh, wN.y, partial);
    hh = fminf(fmaxf(r1.x + bb.z, 0.f), 1.f); partial = fmaf(hh, wN.z, partial);
    hh = fminf(fmaxf(r1.y + bb.w, 0.f), 1.f); partial = fmaf(hh, wN.w, partial);

    // warp reduce
    #pragma unroll
    for (int off = 16; off > 0; off >>= 1)
        partial += __shfl_xor_sync(FULL_MASK, partial, off);

    if (lane == 0) s_partial[w] = partial;
    __syncthreads();

    // warp 0 combines the 8 warp partials and finalizes
    if (tid < 32) {
        float p = (lane < 8) ? s_partial[lane] : 0.0f;
        #pragma unroll
        for (int off = 4; off > 0; off >>= 1)
            p += __shfl_xor_sync(FULL_MASK, p, off);
        if (lane == 0) {
            float x = p + out_b[0];
            out[b] = 1.0f / (1.0f + __expf(-x));
        }
    }
}

// ---------------------------------------------------------------------------
// kernel_launch
// Inputs: values, stm_indices, nstm_indices, ft_w, ft_b, out_w, out_b
// ---------------------------------------------------------------------------
extern "C" void kernel_launch(void* const* d_in, const int* in_sizes, int n_in,
                              void* d_out, int out_size)
{
    const float* values   = (const float*)d_in[0];
    const int*   stm_idx  = (const int*)  d_in[1];
    const int*   nstm_idx = (const int*)  d_in[2];
    const float* ft_w     = (const float*)d_in[3];
    const float* ft_b     = (const float*)d_in[4];
    const float* out_w    = (const float*)d_in[5];
    const float* out_b    = (const float*)d_in[6];
    float*       out      = (float*)d_out;

    convert_ftw_kernel<<<(NFEAT * FT_OUT / 4) / 256, 256>>>(ft_w);
    // one sample per CTA
    nnue_main_kernel<<<BATCH, 256>>>(values, stm_idx, nstm_idx,
                                     ft_b, out_w, out_b, out);
}